// round 2
// baseline (speedup 1.0000x reference)
#include <cuda_runtime.h>

// SingleLayerLSTM: B=128, T=512, IN=128, H=1024, OUT=64.
// Persistent kernel, 128 CTAs x 256 threads, hand-rolled grid barrier.
// CTA (bt, hs): batch rows [bt*32, bt*32+32), hidden slice [hs*32, hs*32+32).
// Per step: CTA computes a 32x128 tile of pre-activations where the 128 cols
// are the 4 gates (f,i,z from kernel_fiz; r from kernel_r) for its hidden
// slice, so gate combination + cell update is CTA-local. c lives in registers
// for all 512 steps. h is double-buffered in a __device__ array (L2-coherent
// via __ldcg/__stcg + threadfence in the barrier).

#define BB 128
#define TT 512
#define IND 128
#define HH 1024
#define OUTD 64
#define NCTA 128
#define NTHR 256
#define KB 32
#define NCHUNK 36   // 1152 / 32

__device__ float g_h[2][BB * HH];          // double-buffered hidden state
__device__ unsigned int g_bar_count = 0;
__device__ unsigned int g_bar_gen = 0;

__device__ __forceinline__ float sigmoid_(float x) {
    return __fdividef(1.0f, 1.0f + __expf(-x));
}
__device__ __forceinline__ float tanh_(float x) {
    return __fdividef(2.0f, 1.0f + __expf(-2.0f * x)) - 1.0f;
}

// Sense-free monotonic-epoch grid barrier. All 128 CTAs are co-resident
// (grid=128 < 148 SMs, 1 CTA/SM). Arrive via device atomic; poll via
// volatile L2 load (no atomic hammering of one address).
__device__ __forceinline__ void grid_barrier(unsigned int& epoch) {
    __syncthreads();
    if (threadIdx.x == 0) {
        __threadfence();                       // release: h/y writes visible
        unsigned int target = epoch + 1;
        unsigned int arr = atomicAdd(&g_bar_count, 1u);
        if (arr == NCTA - 1) {
            atomicExch(&g_bar_count, 0u);
            __threadfence();
            atomicAdd(&g_bar_gen, 1u);
        } else {
            while ((int)(*(volatile unsigned int*)&g_bar_gen - target) < 0) {
                __nanosleep(64);
            }
        }
        epoch = target;
        __threadfence();                       // acquire
    }
    __syncthreads();
}

__global__ void __launch_bounds__(NTHR, 1)
lstm_kernel(const float* __restrict__ u,      // (B,T,IN)
            const float* __restrict__ x0,     // (B,1,2H)
            const float* __restrict__ kfiz,   // (1152, 3072)
            const float* __restrict__ bfiz,   // (3072)
            const float* __restrict__ kr,     // (1152, 1024)
            const float* __restrict__ br,     // (1024)
            const float* __restrict__ wout,   // (1024, 64)
            const float* __restrict__ bout,   // (64)
            float* __restrict__ y)            // (B,T,OUT)
{
    __shared__ float ws[KB][128];     // weight tile: [kk][gate*32 + cc]
    __shared__ float xs[KB][36];      // x tile: [kk][row], padded to 36 for LDS.128
    __shared__ float pre[32][128];    // pre-activations
    __shared__ float sred[NTHR];      // y reduction

    const int tid = threadIdx.x;
    const int bid = blockIdx.x;
    const int b0 = (bid >> 5) * 32;   // batch tile base
    const int hb = (bid & 31) * 32;   // hidden slice base

    // GEMM microtile: thread -> 4 rows x 4 cols of the 32x128 tile
    const int cb = (tid & 31) * 4;    // local col base (0..124)
    const int rb = (tid >> 5) * 4;    // local row base (0..28)

    // combine-phase mapping: thread -> (row crow, 4 hidden idx chh..chh+3)
    const int crow = tid >> 3;        // 0..31
    const int chh = (tid & 7) * 4;    // 0..28

    unsigned int epoch = 0;
    if (tid == 0) epoch = *(volatile unsigned int*)&g_bar_gen;

    // Init c (registers, persistent) and h buffer 0 from x0 = [h0 | c0]
    float4 c_reg = *(const float4*)&x0[(size_t)(b0 + crow) * (2 * HH) + HH + hb + chh];
    {
        float4 h0 = *(const float4*)&x0[(size_t)(b0 + crow) * (2 * HH) + hb + chh];
        __stcg((float4*)&g_h[0][(b0 + crow) * HH + hb + chh], h0);
    }

    // Per-thread bias for its 4 output columns (same for all rows)
    const int bgate = cb >> 5;
    const int bcc = cb & 31;
    float4 biasv = (bgate < 3) ? *(const float4*)&bfiz[bgate * HH + hb + bcc]
                               : *(const float4*)&br[hb + bcc];

    // Weight-load addressing (constant across steps)
    const int wkk0 = tid >> 5;                // kk base (0..7), +0/8/16/24
    const int wcol = (tid & 31) * 4;          // tile col (0..124)
    const int wg = wcol >> 5;                 // gate 0..3
    const int wcc = wcol & 31;
    const float* wbase = (wg < 3) ? (kfiz + wg * HH + hb + wcc) : (kr + hb + wcc);
    const int wstride = (wg < 3) ? (3 * HH) : HH;

    grid_barrier(epoch);   // h0 visible to all CTAs

    float4 wreg[4];
    float xreg[4];

    for (int t = 0; t < TT; ++t) {
        const float* hcur = g_h[t & 1];
        float* hnext = g_h[(t + 1) & 1];

        float acc[4][4];
        #pragma unroll
        for (int i = 0; i < 4; ++i) {
            acc[i][0] = biasv.x; acc[i][1] = biasv.y;
            acc[i][2] = biasv.z; acc[i][3] = biasv.w;
        }

        // ---- prefetch chunk 0 (k in [0,32): always from u) ----
        {
            #pragma unroll
            for (int i = 0; i < 4; ++i) {
                int k = wkk0 + i * 8;
                wreg[i] = *(const float4*)(wbase + (size_t)k * wstride);
            }
            int kx = tid & 31;
            int r0 = tid >> 5;
            #pragma unroll
            for (int i = 0; i < 4; ++i) {
                int r = r0 + i * 8;
                xreg[i] = u[((size_t)(b0 + r) * TT + t) * IND + kx];
            }
        }

        for (int c = 0; c < NCHUNK; ++c) {
            // store prefetched chunk to smem
            #pragma unroll
            for (int i = 0; i < 4; ++i)
                *(float4*)&ws[wkk0 + i * 8][wcol] = wreg[i];
            {
                int kk = tid & 31;
                int r0 = tid >> 5;
                #pragma unroll
                for (int i = 0; i < 4; ++i)
                    xs[kk][r0 + i * 8] = xreg[i];
            }
            __syncthreads();

            // issue next chunk's global loads (latency hidden by compute)
            if (c + 1 < NCHUNK) {
                const int k0 = (c + 1) * KB;
                #pragma unroll
                for (int i = 0; i < 4; ++i) {
                    int k = k0 + wkk0 + i * 8;
                    wreg[i] = *(const float4*)(wbase + (size_t)k * wstride);
                }
                int kx = k0 + (tid & 31);
                int r0 = tid >> 5;
                #pragma unroll
                for (int i = 0; i < 4; ++i) {
                    int r = r0 + i * 8;
                    if (kx < IND)
                        xreg[i] = u[((size_t)(b0 + r) * TT + t) * IND + kx];
                    else
                        xreg[i] = __ldcg(&hcur[(b0 + r) * HH + (kx - IND)]);
                }
            }

            // compute 32 k-iterations from smem
            #pragma unroll 8
            for (int kk = 0; kk < KB; ++kk) {
                float4 wv = *(float4*)&ws[kk][cb];
                float4 xv = *(float4*)&xs[kk][rb];
                acc[0][0] += xv.x * wv.x; acc[0][1] += xv.x * wv.y;
                acc[0][2] += xv.x * wv.z; acc[0][3] += xv.x * wv.w;
                acc[1][0] += xv.y * wv.x; acc[1][1] += xv.y * wv.y;
                acc[1][2] += xv.y * wv.z; acc[1][3] += xv.y * wv.w;
                acc[2][0] += xv.z * wv.x; acc[2][1] += xv.z * wv.y;
                acc[2][2] += xv.z * wv.z; acc[2][3] += xv.z * wv.w;
                acc[3][0] += xv.w * wv.x; acc[3][1] += xv.w * wv.y;
                acc[3][2] += xv.w * wv.z; acc[3][3] += xv.w * wv.w;
            }
            __syncthreads();
        }

        // ---- pre-activations to smem ----
        #pragma unroll
        for (int i = 0; i < 4; ++i) {
            float4 v = make_float4(acc[i][0], acc[i][1], acc[i][2], acc[i][3]);
            *(float4*)&pre[rb + i][cb] = v;
        }
        __syncthreads();

        // ---- gate combine + cell update (c register-resident) ----
        {
            float4 fv = *(float4*)&pre[crow][chh];
            float4 iv = *(float4*)&pre[crow][32 + chh];
            float4 zv = *(float4*)&pre[crow][64 + chh];
            float4 rv = *(float4*)&pre[crow][96 + chh];
            float4 hn;
            c_reg.x = sigmoid_(fv.x) * c_reg.x + sigmoid_(iv.x) * tanh_(rv.x);
            hn.x = sigmoid_(zv.x) * tanh_(c_reg.x);
            c_reg.y = sigmoid_(fv.y) * c_reg.y + sigmoid_(iv.y) * tanh_(rv.y);
            hn.y = sigmoid_(zv.y) * tanh_(c_reg.y);
            c_reg.z = sigmoid_(fv.z) * c_reg.z + sigmoid_(iv.z) * tanh_(rv.z);
            hn.z = sigmoid_(zv.z) * tanh_(c_reg.z);
            c_reg.w = sigmoid_(fv.w) * c_reg.w + sigmoid_(iv.w) * tanh_(rv.w);
            hn.w = sigmoid_(zv.w) * tanh_(c_reg.w);
            __stcg((float4*)&hnext[(b0 + crow) * HH + hb + chh], hn);
        }

        // ---- y(t-1) = h(t-1) @ W_out + b_out; CTA bid handles batch row bid
        if (t > 0) {
            const float* hrow = &hcur[bid * HH];
            int o = tid & 63;
            int kbas = (tid >> 6) * 256;
            float p = 0.0f;
            #pragma unroll 4
            for (int i = 0; i < 256; ++i) {
                p += __ldcg(&hrow[kbas + i]) * wout[(kbas + i) * OUTD + o];
            }
            sred[tid] = p;
            __syncthreads();
            if (tid < 64) {
                float s = sred[tid] + sred[tid + 64] + sred[tid + 128] + sred[tid + 192]
                        + bout[tid];
                y[((size_t)bid * TT + (t - 1)) * OUTD + tid] = s;
            }
        }

        grid_barrier(epoch);
    }

    // ---- final y(T-1) from g_h[0] (= h after step 511) ----
    {
        const float* hrow = &g_h[0][bid * HH];
        int o = tid & 63;
        int kbas = (tid >> 6) * 256;
        float p = 0.0f;
        #pragma unroll 4
        for (int i = 0; i < 256; ++i) {
            p += __ldcg(&hrow[kbas + i]) * wout[(kbas + i) * OUTD + o];
        }
        sred[tid] = p;
        __syncthreads();
        if (tid < 64) {
            float s = sred[tid] + sred[tid + 64] + sred[tid + 128] + sred[tid + 192]
                    + bout[tid];
            y[((size_t)bid * TT + (TT - 1)) * OUTD + tid] = s;
        }
    }
}

extern "C" void kernel_launch(void* const* d_in, const int* in_sizes, int n_in,
                              void* d_out, int out_size) {
    (void)in_sizes; (void)n_in; (void)out_size;
    lstm_kernel<<<NCTA, NTHR>>>(
        (const float*)d_in[0],   // u
        (const float*)d_in[1],   // x0
        (const float*)d_in[2],   // kernel_fiz
        (const float*)d_in[3],   // bias_fiz
        (const float*)d_in[4],   // kernel_r
        (const float*)d_in[5],   // bias_r
        (const float*)d_in[6],   // W_out
        (const float*)d_in[7],   // b_out
        (float*)d_out);
}

// round 4
// speedup vs baseline: 4.9840x; 4.9840x over previous
#include <cuda_runtime.h>
#include <cuda_bf16.h>
#include <cstdint>

#define TT 512
#define BATCH 128
#define IND 128
#define HH 1024
#define OUTD 64
#define NCTA 130
#define NTHR 256
#define NCHUNK 18
#define KCH 64
#define NKS 72                      // 1152 / 16 k-steps

#define OFF_BIAS 0
#define OFF_ABUF 1024
#define ATILE 16384                 // 128x64 bf16
#define ABUF_STRIDE 32768           // hi + lo
#define OFF_BFRAG (OFF_ABUF + 2 * ABUF_STRIDE)
#define BFRAG_SZ (NKS * 4 * 32 * 8) // 73728
#define SMEM_TOTAL (OFF_BFRAG + 2 * BFRAG_SZ)   // 214016

__device__ __align__(16) __nv_bfloat16 g_u_hi[(size_t)TT * BATCH * IND];
__device__ __align__(16) __nv_bfloat16 g_u_lo[(size_t)TT * BATCH * IND];
__device__ __align__(16) __nv_bfloat16 g_h_hi[2][BATCH * HH];
__device__ __align__(16) __nv_bfloat16 g_h_lo[2][BATCH * HH];
__device__ unsigned int g_bar_count = 0;
__device__ unsigned int g_bar_gen = 0;

#define SWZ128(b) ((b) ^ (((b) >> 3) & 0x70))

__device__ __forceinline__ uint32_t smem_u32(const void* p) {
    uint32_t a;
    asm("{ .reg .u64 t; cvta.to.shared.u64 t, %1; cvt.u32.u64 %0, t; }" : "=r"(a) : "l"(p));
    return a;
}

__device__ __forceinline__ float sg(float x) { return __fdividef(1.0f, 1.0f + __expf(-x)); }
__device__ __forceinline__ float th(float x) { return __fdividef(2.0f, 1.0f + __expf(-2.0f * x)) - 1.0f; }

// pack hi bf16x2 (a low, b high); lo residual pair out-param
__device__ __forceinline__ uint32_t pkbf(float a, float b, uint32_t& lo) {
    __nv_bfloat16 ah = __float2bfloat16_rn(a), bh = __float2bfloat16_rn(b);
    __nv_bfloat16 al = __float2bfloat16_rn(a - __bfloat162float(ah));
    __nv_bfloat16 bl = __float2bfloat16_rn(b - __bfloat162float(bh));
    lo = (uint32_t)__bfloat16_as_ushort(al) | ((uint32_t)__bfloat16_as_ushort(bl) << 16);
    return (uint32_t)__bfloat16_as_ushort(ah) | ((uint32_t)__bfloat16_as_ushort(bh) << 16);
}

__device__ __forceinline__ void ldsm_x4(uint32_t* r, uint32_t addr) {
    asm volatile("ldmatrix.sync.aligned.m8n8.x4.shared.b16 {%0,%1,%2,%3}, [%4];"
        : "=r"(r[0]), "=r"(r[1]), "=r"(r[2]), "=r"(r[3]) : "r"(addr));
}

__device__ __forceinline__ void mma_bf16(float* d, const uint32_t* a, uint32_t b0, uint32_t b1) {
    asm volatile(
        "mma.sync.aligned.m16n8k16.row.col.f32.bf16.bf16.f32 "
        "{%0,%1,%2,%3}, {%4,%5,%6,%7}, {%8,%9}, {%0,%1,%2,%3};"
        : "+f"(d[0]), "+f"(d[1]), "+f"(d[2]), "+f"(d[3])
        : "r"(a[0]), "r"(a[1]), "r"(a[2]), "r"(a[3]), "r"(b0), "r"(b1));
}

__device__ __forceinline__ void grid_barrier(unsigned int& epoch) {
    __syncthreads();
    if (threadIdx.x == 0) {
        __threadfence();
        unsigned int target = epoch + 1;
        unsigned int arr = atomicAdd(&g_bar_count, 1u);
        if (arr == NCTA - 1) {
            atomicExch(&g_bar_count, 0u);
            __threadfence();
            atomicAdd(&g_bar_gen, 1u);
        } else {
            while ((int)(*(volatile unsigned int*)&g_bar_gen - target) < 0) __nanosleep(32);
        }
        epoch = target;
        __threadfence();
    }
    __syncthreads();
}

__device__ __forceinline__ void load_chunk(int tt, int c,
    const __nv_bfloat16* hHi, const __nv_bfloat16* hLo,
    int tid, uint4* vhi, uint4* vlo)
{
    const __nv_bfloat16 *srcH, *srcL;
    int rstride;
    if (c < 2) {
        size_t base = (size_t)tt * BATCH * IND + c * KCH;
        srcH = g_u_hi + base; srcL = g_u_lo + base; rstride = IND;
    } else {
        srcH = hHi + (size_t)(c - 2) * KCH;
        srcL = hLo + (size_t)(c - 2) * KCH;
        rstride = HH;
    }
    #pragma unroll
    for (int i = 0; i < 4; ++i) {
        int f = tid + NTHR * i;
        int row = f >> 3, seg = f & 7;
        vhi[i] = __ldcg((const uint4*)(srcH + (size_t)row * rstride + seg * 8));
        vlo[i] = __ldcg((const uint4*)(srcL + (size_t)row * rstride + seg * 8));
    }
}

__global__ void __launch_bounds__(NTHR, 1)
lstm_mma(const float* __restrict__ u, const float* __restrict__ x0,
         const float* __restrict__ kfiz, const float* __restrict__ bfiz,
         const float* __restrict__ kr, const float* __restrict__ br,
         const float* __restrict__ wout, const float* __restrict__ bout,
         float* __restrict__ y)
{
    extern __shared__ char smem[];
    const int tid = threadIdx.x;
    const int bid = blockIdx.x;
    const int warp = tid >> 5, lane = tid & 31;
    const int gid = lane >> 2, tig = lane & 3;
    const int j0 = tig * 2;
    const uint32_t sb = smem_u32(smem);
    float* bias_s = (float*)(smem + OFF_BIAS);

    // ---- init: weights -> smem B fragments (mma layout, bf16 hi/lo) ----
    // idx = s*128 + nt*32 + l; lane l: n = nt*8 + (l>>2), k0 = s*16 + (l&3)*2
    // reg0 = (k0,k0+1), reg1 = (k0+8,k0+9)  [m16n8k16 .col B fragment]
    for (int idx = tid; idx < NKS * 4 * 32; idx += NTHR) {
        int l = idx & 31;
        int nt = (idx >> 5) & 3;
        int s = idx >> 7;
        int nloc = nt * 8 + (l >> 2);
        int k0 = s * 16 + (l & 3) * 2;
        float w[4];
        #pragma unroll
        for (int q = 0; q < 4; ++q) {
            int k = k0 + (q >> 1) * 8 + (q & 1);
            float v;
            if (bid < 128) {
                int g = nloc >> 3, hid = bid * 8 + (nloc & 7);
                v = (g < 3) ? kfiz[(size_t)k * 3072 + g * 1024 + hid]
                            : kr[(size_t)k * 1024 + hid];
            } else {
                int col = (bid - 128) * 32 + nloc;
                v = (k < IND) ? 0.0f : wout[(size_t)(k - IND) * OUTD + col];
            }
            w[q] = v;
        }
        uint32_t lo0, lo1;
        uint32_t h0 = pkbf(w[0], w[1], lo0);
        uint32_t h1 = pkbf(w[2], w[3], lo1);
        uint32_t off = (uint32_t)idx * 8;
        *(uint2*)(smem + OFF_BFRAG + off) = make_uint2(h0, h1);
        *(uint2*)(smem + OFF_BFRAG + BFRAG_SZ + off) = make_uint2(lo0, lo1);
    }
    if (tid < 32) {
        float bv;
        if (bid < 128) {
            int g = tid >> 3, hid = bid * 8 + (tid & 7);
            bv = (g < 3) ? bfiz[g * 1024 + hid] : br[hid];
        } else bv = bout[(bid - 128) * 32 + tid];
        bias_s[tid] = bv;
    }

    // ---- init: u -> (t,b,k) bf16 hi/lo, grid-strided ----
    {
        const size_t UN = (size_t)TT * BATCH * IND;
        for (size_t i = (size_t)bid * NTHR + tid; i < UN; i += (size_t)NCTA * NTHR) {
            int b = (int)(i / (TT * IND));
            int rem = (int)(i % (TT * IND));
            float w = u[i];
            __nv_bfloat16 hi = __float2bfloat16_rn(w);
            size_t o = ((size_t)(rem / IND) * BATCH + b) * IND + (rem % IND);
            g_u_hi[o] = hi;
            g_u_lo[o] = __float2bfloat16_rn(w - __bfloat162float(hi));
        }
    }

    // ---- init: c0 (registers, per-lane 4 values), h0 -> g_h[0] ----
    const int r0 = warp * 16 + gid, r1 = r0 + 8;
    float creg[4];
    if (bid < 128) {
        creg[0] = x0[(size_t)r0 * 2 * HH + HH + bid * 8 + j0];
        creg[1] = x0[(size_t)r0 * 2 * HH + HH + bid * 8 + j0 + 1];
        creg[2] = x0[(size_t)r1 * 2 * HH + HH + bid * 8 + j0];
        creg[3] = x0[(size_t)r1 * 2 * HH + HH + bid * 8 + j0 + 1];
        if (tid < 128) {   // thread = batch row; write this CTA's 8 units
            const float* xp = x0 + (size_t)tid * 2 * HH;
            uint32_t hh[4], ll[4];
            #pragma unroll
            for (int q = 0; q < 4; ++q)
                hh[q] = pkbf(xp[bid * 8 + 2 * q], xp[bid * 8 + 2 * q + 1], ll[q]);
            size_t ho = (size_t)tid * HH + bid * 8;
            __stcg((uint4*)(g_h_hi[0] + ho), make_uint4(hh[0], hh[1], hh[2], hh[3]));
            __stcg((uint4*)(g_h_lo[0] + ho), make_uint4(ll[0], ll[1], ll[2], ll[3]));
        }
    }

    unsigned int epoch = 0;
    if (tid == 0) epoch = *(volatile unsigned int*)&g_bar_gen;
    grid_barrier(epoch);   // init data globally visible

    // per-lane bias for C cols (nt*8 + tig*2 + e)
    float bcol[4][2];
    #pragma unroll
    for (int nt = 0; nt < 4; ++nt) {
        bcol[nt][0] = bias_s[nt * 8 + j0];
        bcol[nt][1] = bias_s[nt * 8 + j0 + 1];
    }

    // ldmatrix address offsets (per lane, constant across chunks)
    // mat = lane>>3: rowA = warp*16 + (lane&7) + (mat&1)*8, colhalf = mat>>1
    uint32_t aoff[4];
    {
        int mat = lane >> 3;
        int rowA = warp * 16 + (lane & 7) + (mat & 1) * 8;
        int ch = mat >> 1;
        uint32_t base = (uint32_t)rowA * 128 + ch * 16;
        uint32_t swc = (base >> 3) & 0x70;
        #pragma unroll
        for (int kk = 0; kk < 4; ++kk) aoff[kk] = (base + kk * 32) ^ swc;
    }
    // A-store offsets (per thread, swizzled)
    uint32_t soff[4];
    #pragma unroll
    for (int i = 0; i < 4; ++i) {
        int f = tid + NTHR * i;
        soff[i] = SWZ128((uint32_t)((f >> 3) * 128 + (f & 7) * 16));
    }

    const char* bfh = smem + OFF_BFRAG;
    const char* bfl = smem + OFF_BFRAG + BFRAG_SZ;

    uint4 vhi[4], vlo[4];
    load_chunk(0, 0, nullptr, nullptr, tid, vhi, vlo);   // chunk 0 of t=0 (u)

    for (int t = 0; t <= TT; ++t) {
        const int tt = (t < TT) ? t : (TT - 1);
        const __nv_bfloat16* hHi = g_h_hi[t & 1];
        const __nv_bfloat16* hLo = g_h_lo[t & 1];

        float acc[4][4];
        #pragma unroll
        for (int nt = 0; nt < 4; ++nt)
            #pragma unroll
            for (int q = 0; q < 4; ++q) acc[nt][q] = 0.0f;

        for (int c = 0; c < NCHUNK; ++c) {
            const int buf = c & 1;
            char* abuf = smem + OFF_ABUF + buf * ABUF_STRIDE;
            #pragma unroll
            for (int i = 0; i < 4; ++i) {
                *(uint4*)(abuf + soff[i]) = vhi[i];
                *(uint4*)(abuf + ATILE + soff[i]) = vlo[i];
            }
            __syncthreads();

            if (c + 1 < NCHUNK)
                load_chunk(tt, c + 1, hHi, hLo, tid, vhi, vlo);

            const uint32_t abase = sb + OFF_ABUF + buf * ABUF_STRIDE;
            #pragma unroll
            for (int kk = 0; kk < 4; ++kk) {
                uint32_t ah[4], al[4];
                ldsm_x4(ah, abase + aoff[kk]);
                ldsm_x4(al, abase + ATILE + aoff[kk]);
                int s4 = (c * 4 + kk) * 4;
                #pragma unroll
                for (int nt = 0; nt < 4; ++nt) {
                    uint32_t boff = (uint32_t)((s4 + nt) * 32 + lane) * 8;
                    uint2 bh = *(const uint2*)(bfh + boff);
                    uint2 bl = *(const uint2*)(bfl + boff);
                    mma_bf16(acc[nt], ah, bh.x, bh.y);
                    mma_bf16(acc[nt], ah, bl.x, bl.y);
                    mma_bf16(acc[nt], al, bh.x, bh.y);
                }
            }
            // no trailing sync needed: next store targets the other buffer,
            // and same-buffer reuse is separated by the next chunk's sync.
        }

        // ---- epilogue ----
        if (bid < 128) {
            if (t < TT) {
                float hv[4];
                #pragma unroll
                for (int q = 0; q < 4; ++q) {
                    int e = q & 1;
                    float fp = acc[0][q] + bcol[0][e];
                    float ip = acc[1][q] + bcol[1][e];
                    float zp = acc[2][q] + bcol[2][e];
                    float rp = acc[3][q] + bcol[3][e];
                    creg[q] = sg(fp) * creg[q] + sg(ip) * th(rp);
                    hv[q] = sg(zp) * th(creg[q]);
                }
                int p = (t + 1) & 1;
                uint32_t lo0, lo1;
                uint32_t h0p = pkbf(hv[0], hv[1], lo0);
                uint32_t h1p = pkbf(hv[2], hv[3], lo1);
                size_t o0 = (size_t)r0 * HH + bid * 8 + j0;
                size_t o1 = (size_t)r1 * HH + bid * 8 + j0;
                __stcg((unsigned int*)&g_h_hi[p][o0], h0p);
                __stcg((unsigned int*)&g_h_lo[p][o0], lo0);
                __stcg((unsigned int*)&g_h_hi[p][o1], h1p);
                __stcg((unsigned int*)&g_h_lo[p][o1], lo1);
            }
        } else if (t >= 1) {
            #pragma unroll
            for (int nt = 0; nt < 4; ++nt) {
                int gcol = (bid - 128) * 32 + nt * 8 + j0;
                float2 v0 = make_float2(acc[nt][0] + bcol[nt][0], acc[nt][1] + bcol[nt][1]);
                float2 v1 = make_float2(acc[nt][2] + bcol[nt][0], acc[nt][3] + bcol[nt][1]);
                *(float2*)&y[((size_t)r0 * TT + (t - 1)) * OUTD + gcol] = v0;
                *(float2*)&y[((size_t)r1 * TT + (t - 1)) * OUTD + gcol] = v1;
            }
        }

        // prefetch chunk 0 (u-sourced) of next step before the barrier
        if (t < TT) {
            int tn = (t + 1 < TT) ? (t + 1) : (TT - 1);
            load_chunk(tn, 0, nullptr, nullptr, tid, vhi, vlo);
        }
        grid_barrier(epoch);
    }
}

extern "C" void kernel_launch(void* const* d_in, const int* in_sizes, int n_in,
                              void* d_out, int out_size) {
    (void)in_sizes; (void)n_in; (void)out_size;
    cudaFuncSetAttribute(lstm_mma, cudaFuncAttributeMaxDynamicSharedMemorySize, SMEM_TOTAL);
    lstm_mma<<<NCTA, NTHR, SMEM_TOTAL>>>(
        (const float*)d_in[0], (const float*)d_in[1], (const float*)d_in[2],
        (const float*)d_in[3], (const float*)d_in[4], (const float*)d_in[5],
        (const float*)d_in[6], (const float*)d_in[7], (float*)d_out);
}

// round 5
// speedup vs baseline: 6.0137x; 1.2066x over previous
#include <cuda_runtime.h>
#include <cuda_bf16.h>
#include <cstdint>

#define TT 512
#define BATCH 128
#define IND 128
#define HH 1024
#define OUTD 64
#define NCTA 130
#define NTHR 256
#define NCHUNK 18
#define KCH 64
#define NKS 72                      // 1152 / 16 k-steps

#define OFF_BIAS 0                  // 32 floats + base u32
#define OFF_ABUF 1024
#define ASTAGE 32768                // 8 warps * 4KB (hi 2KB + lo 2KB), per stage
#define OFF_BFRAG (OFF_ABUF + 2 * ASTAGE)       // 66560
#define BFRAG_SZ (NKS * 4 * 32 * 8)             // 73728
#define SMEM_TOTAL (OFF_BFRAG + 2 * BFRAG_SZ)   // 214016

__device__ __align__(16) __nv_bfloat16 g_u_hi[(size_t)TT * BATCH * IND];
__device__ __align__(16) __nv_bfloat16 g_u_lo[(size_t)TT * BATCH * IND];
__device__ __align__(16) __nv_bfloat16 g_h_hi[2][BATCH * HH];
__device__ __align__(16) __nv_bfloat16 g_h_lo[2][BATCH * HH];
__device__ unsigned int g_bar_count = 0;
__device__ unsigned int g_bar_gen = 0;

#define SWZ128(b) ((b) ^ (((b) >> 3) & 0x70))

__device__ __forceinline__ uint32_t smem_u32(const void* p) {
    uint32_t a;
    asm("{ .reg .u64 t; cvta.to.shared.u64 t, %1; cvt.u32.u64 %0, t; }" : "=r"(a) : "l"(p));
    return a;
}

__device__ __forceinline__ float sg(float x) { return __fdividef(1.0f, 1.0f + __expf(-x)); }
__device__ __forceinline__ float th(float x) { return __fdividef(2.0f, 1.0f + __expf(-2.0f * x)) - 1.0f; }

__device__ __forceinline__ uint32_t pkbf(float a, float b, uint32_t& lo) {
    __nv_bfloat16 ah = __float2bfloat16_rn(a), bh = __float2bfloat16_rn(b);
    __nv_bfloat16 al = __float2bfloat16_rn(a - __bfloat162float(ah));
    __nv_bfloat16 bl = __float2bfloat16_rn(b - __bfloat162float(bh));
    lo = (uint32_t)__bfloat16_as_ushort(al) | ((uint32_t)__bfloat16_as_ushort(bl) << 16);
    return (uint32_t)__bfloat16_as_ushort(ah) | ((uint32_t)__bfloat16_as_ushort(bh) << 16);
}

__device__ __forceinline__ void ldsm_x4(uint32_t* r, uint32_t addr) {
    asm volatile("ldmatrix.sync.aligned.m8n8.x4.shared.b16 {%0,%1,%2,%3}, [%4];"
        : "=r"(r[0]), "=r"(r[1]), "=r"(r[2]), "=r"(r[3]) : "r"(addr));
}

__device__ __forceinline__ void mma_bf16(float* d, const uint32_t* a, uint32_t b0, uint32_t b1) {
    asm volatile(
        "mma.sync.aligned.m16n8k16.row.col.f32.bf16.bf16.f32 "
        "{%0,%1,%2,%3}, {%4,%5,%6,%7}, {%8,%9}, {%0,%1,%2,%3};"
        : "+f"(d[0]), "+f"(d[1]), "+f"(d[2]), "+f"(d[3])
        : "r"(a[0]), "r"(a[1]), "r"(a[2]), "r"(a[3]), "r"(b0), "r"(b1));
}

// full barrier (init only)
__device__ __forceinline__ void grid_barrier_full(unsigned int& epoch) {
    __syncthreads();
    if (threadIdx.x == 0) {
        __threadfence();
        unsigned int target = epoch + 1;
        unsigned int arr = atomicAdd(&g_bar_count, 1u);
        if (arr == NCTA - 1) {
            atomicExch(&g_bar_count, 0u);
            __threadfence();
            atomicAdd(&g_bar_gen, 1u);
        } else {
            while ((int)(*(volatile unsigned int*)&g_bar_gen - target) < 0) __nanosleep(32);
        }
        epoch = target;
        __threadfence();
    }
    __syncthreads();
}

// split barrier: arrive (tid0, after __syncthreads) ... wait later per-warp
__device__ __forceinline__ void bar_arrive() {
    if (threadIdx.x == 0) {
        __threadfence();
        unsigned int arr = atomicAdd(&g_bar_count, 1u);
        if (arr == NCTA - 1) {
            atomicExch(&g_bar_count, 0u);
            __threadfence();
            atomicAdd(&g_bar_gen, 1u);
        }
    }
}
__device__ __forceinline__ void bar_wait(unsigned int target) {
    while ((int)(*(volatile unsigned int*)&g_bar_gen - target) < 0) { }
    __threadfence();
}

// per-warp chunk load: warp's 16 rows x 64 k, hi+lo, into registers
__device__ __forceinline__ void load_chunk_w(int tt, int c,
    const __nv_bfloat16* hHi, const __nv_bfloat16* hLo,
    int warp, int lane, uint4* vhi, uint4* vlo)
{
    const __nv_bfloat16 *srcH, *srcL;
    int rstride;
    if (c < 2) {
        size_t base = (size_t)tt * BATCH * IND + c * KCH;
        srcH = g_u_hi + base; srcL = g_u_lo + base; rstride = IND;
    } else {
        srcH = hHi + (size_t)(c - 2) * KCH;
        srcL = hLo + (size_t)(c - 2) * KCH;
        rstride = HH;
    }
    const int seg = lane & 7;
    const int rb = warp * 16 + (lane >> 3);
    #pragma unroll
    for (int i = 0; i < 4; ++i) {
        int row = rb + 4 * i;
        vhi[i] = __ldcg((const uint4*)(srcH + (size_t)row * rstride + seg * 8));
        vlo[i] = __ldcg((const uint4*)(srcL + (size_t)row * rstride + seg * 8));
    }
}

__global__ void __launch_bounds__(NTHR, 1)
lstm_mma(const float* __restrict__ u, const float* __restrict__ x0,
         const float* __restrict__ kfiz, const float* __restrict__ bfiz,
         const float* __restrict__ kr, const float* __restrict__ br,
         const float* __restrict__ wout, const float* __restrict__ bout,
         float* __restrict__ y)
{
    extern __shared__ char smem[];
    const int tid = threadIdx.x;
    const int bid = blockIdx.x;
    const int warp = tid >> 5, lane = tid & 31;
    const int gid = lane >> 2, tig = lane & 3;
    const int j0 = tig * 2;
    const uint32_t sb = smem_u32(smem);
    float* bias_s = (float*)(smem + OFF_BIAS);
    unsigned int* base_s = (unsigned int*)(smem + OFF_BIAS + 512);

    // ---- init: weights -> smem B fragments (mma .col layout, bf16 hi/lo) ----
    for (int idx = tid; idx < NKS * 4 * 32; idx += NTHR) {
        int l = idx & 31;
        int nt = (idx >> 5) & 3;
        int s = idx >> 7;
        int nloc = nt * 8 + (l >> 2);
        int k0 = s * 16 + (l & 3) * 2;
        float w[4];
        #pragma unroll
        for (int q = 0; q < 4; ++q) {
            int k = k0 + (q >> 1) * 8 + (q & 1);
            float v;
            if (bid < 128) {
                int g = nloc >> 3, hid = bid * 8 + (nloc & 7);
                v = (g < 3) ? kfiz[(size_t)k * 3072 + g * 1024 + hid]
                            : kr[(size_t)k * 1024 + hid];
            } else {
                int col = (bid - 128) * 32 + nloc;
                v = (k < IND) ? 0.0f : wout[(size_t)(k - IND) * OUTD + col];
            }
            w[q] = v;
        }
        uint32_t lo0, lo1;
        uint32_t h0 = pkbf(w[0], w[1], lo0);
        uint32_t h1 = pkbf(w[2], w[3], lo1);
        uint32_t off = (uint32_t)idx * 8;
        *(uint2*)(smem + OFF_BFRAG + off) = make_uint2(h0, h1);
        *(uint2*)(smem + OFF_BFRAG + BFRAG_SZ + off) = make_uint2(lo0, lo1);
    }
    if (tid < 32) {
        float bv;
        if (bid < 128) {
            int g = tid >> 3, hid = bid * 8 + (tid & 7);
            bv = (g < 3) ? bfiz[g * 1024 + hid] : br[hid];
        } else bv = bout[(bid - 128) * 32 + tid];
        bias_s[tid] = bv;
    }

    // ---- init: u -> (t,b,k) bf16 hi/lo, grid-strided ----
    {
        const size_t UN = (size_t)TT * BATCH * IND;
        for (size_t i = (size_t)bid * NTHR + tid; i < UN; i += (size_t)NCTA * NTHR) {
            int b = (int)(i / (TT * IND));
            int rem = (int)(i % (TT * IND));
            float w = u[i];
            __nv_bfloat16 hi = __float2bfloat16_rn(w);
            size_t o = ((size_t)(rem / IND) * BATCH + b) * IND + (rem % IND);
            g_u_hi[o] = hi;
            g_u_lo[o] = __float2bfloat16_rn(w - __bfloat162float(hi));
        }
    }

    // ---- init: c0 (per-lane 4 values), h0 -> g_h[0] ----
    const int r0 = warp * 16 + gid, r1 = r0 + 8;
    float creg[4];
    if (bid < 128) {
        creg[0] = x0[(size_t)r0 * 2 * HH + HH + bid * 8 + j0];
        creg[1] = x0[(size_t)r0 * 2 * HH + HH + bid * 8 + j0 + 1];
        creg[2] = x0[(size_t)r1 * 2 * HH + HH + bid * 8 + j0];
        creg[3] = x0[(size_t)r1 * 2 * HH + HH + bid * 8 + j0 + 1];
        if (tid < 128) {
            const float* xp = x0 + (size_t)tid * 2 * HH;
            uint32_t hh[4], ll[4];
            #pragma unroll
            for (int q = 0; q < 4; ++q)
                hh[q] = pkbf(xp[bid * 8 + 2 * q], xp[bid * 8 + 2 * q + 1], ll[q]);
            size_t ho = (size_t)tid * HH + bid * 8;
            __stcg((uint4*)(g_h_hi[0] + ho), make_uint4(hh[0], hh[1], hh[2], hh[3]));
            __stcg((uint4*)(g_h_lo[0] + ho), make_uint4(ll[0], ll[1], ll[2], ll[3]));
        }
    }

    unsigned int epoch = 0;
    if (tid == 0) epoch = *(volatile unsigned int*)&g_bar_gen;
    grid_barrier_full(epoch);               // init data globally visible
    if (tid == 0) *base_s = epoch;
    __syncthreads();
    const unsigned int base = *base_s;

    // per-lane bias for C cols
    float bcol[4][2];
    #pragma unroll
    for (int nt = 0; nt < 4; ++nt) {
        bcol[nt][0] = bias_s[nt * 8 + j0];
        bcol[nt][1] = bias_s[nt * 8 + j0 + 1];
    }

    // ldmatrix offsets within warp slot (16 rows x 128B, swizzled)
    uint32_t aoff[4];
    {
        int mat = lane >> 3;
        int rloc = (lane & 7) + (mat & 1) * 8;
        int ch = mat >> 1;
        uint32_t b0 = (uint32_t)rloc * 128 + ch * 16;
        uint32_t swc = (b0 >> 3) & 0x70;
        #pragma unroll
        for (int kk = 0; kk < 4; ++kk) aoff[kk] = (b0 + kk * 32) ^ swc;
    }
    // store offsets within warp slot (swizzled)
    uint32_t soff[4];
    {
        const int seg = lane & 7;
        #pragma unroll
        for (int i = 0; i < 4; ++i) {
            uint32_t b0 = (uint32_t)((lane >> 3) + 4 * i) * 128 + seg * 16;
            soff[i] = SWZ128(b0);
        }
    }

    const char* bfh = smem + OFF_BFRAG;
    const char* bfl = smem + OFF_BFRAG + BFRAG_SZ;
    const uint32_t slot0 = sb + OFF_ABUF + warp * 4096;

    uint4 vhi[4], vlo[4];
    load_chunk_w(0, 0, nullptr, nullptr, warp, lane, vhi, vlo);

    for (int t = 0; t <= TT; ++t) {
        const int tt = (t < TT) ? t : (TT - 1);
        const __nv_bfloat16* hHi = g_h_hi[t & 1];
        const __nv_bfloat16* hLo = g_h_lo[t & 1];

        float acc[4][4];
        #pragma unroll
        for (int nt = 0; nt < 4; ++nt)
            #pragma unroll
            for (int q = 0; q < 4; ++q) acc[nt][q] = 0.0f;

        for (int c = 0; c < NCHUNK; ++c) {
            const uint32_t slot = slot0 + (uint32_t)(c & 1) * ASTAGE;
            char* sp = smem + (slot - sb);
            #pragma unroll
            for (int i = 0; i < 4; ++i) {
                *(uint4*)(sp + soff[i]) = vhi[i];
                *(uint4*)(sp + 2048 + soff[i]) = vlo[i];
            }
            __syncwarp();

            if (c + 1 < NCHUNK) {
                if (c + 1 == 2) bar_wait(base + t);   // h(t) published
                load_chunk_w(tt, c + 1, hHi, hLo, warp, lane, vhi, vlo);
            } else if (t < TT) {
                int tn = (t + 1 < TT) ? (t + 1) : (TT - 1);
                load_chunk_w(tn, 0, nullptr, nullptr, warp, lane, vhi, vlo);
            }

            #pragma unroll
            for (int kk = 0; kk < 4; ++kk) {
                uint32_t ah[4], al[4];
                ldsm_x4(ah, slot + aoff[kk]);
                ldsm_x4(al, slot + 2048 + aoff[kk]);
                int s4 = (c * 4 + kk) * 4;
                #pragma unroll
                for (int nt = 0; nt < 4; ++nt) {
                    uint32_t boff = (uint32_t)((s4 + nt) * 32 + lane) * 8;
                    uint2 bh = *(const uint2*)(bfh + boff);
                    uint2 bl = *(const uint2*)(bfl + boff);
                    mma_bf16(acc[nt], ah, bh.x, bh.y);
                    mma_bf16(acc[nt], ah, bl.x, bl.y);
                    mma_bf16(acc[nt], al, bh.x, bh.y);
                }
            }
        }

        // ---- warp-local epilogue ----
        if (bid < 128) {
            if (t < TT) {
                float hv[4];
                #pragma unroll
                for (int q = 0; q < 4; ++q) {
                    int e = q & 1;
                    float fp = acc[0][q] + bcol[0][e];
                    float ip = acc[1][q] + bcol[1][e];
                    float zp = acc[2][q] + bcol[2][e];
                    float rp = acc[3][q] + bcol[3][e];
                    creg[q] = sg(fp) * creg[q] + sg(ip) * th(rp);
                    hv[q] = sg(zp) * th(creg[q]);
                }
                int p = (t + 1) & 1;
                uint32_t lo0, lo1;
                uint32_t h0p = pkbf(hv[0], hv[1], lo0);
                uint32_t h1p = pkbf(hv[2], hv[3], lo1);
                size_t o0 = (size_t)r0 * HH + bid * 8 + j0;
                size_t o1 = (size_t)r1 * HH + bid * 8 + j0;
                __stcg((unsigned int*)&g_h_hi[p][o0], h0p);
                __stcg((unsigned int*)&g_h_lo[p][o0], lo0);
                __stcg((unsigned int*)&g_h_hi[p][o1], h1p);
                __stcg((unsigned int*)&g_h_lo[p][o1], lo1);
            }
        } else if (t >= 1) {
            #pragma unroll
            for (int nt = 0; nt < 4; ++nt) {
                int gcol = (bid - 128) * 32 + nt * 8 + j0;
                float2 v0 = make_float2(acc[nt][0] + bcol[nt][0], acc[nt][1] + bcol[nt][1]);
                float2 v1 = make_float2(acc[nt][2] + bcol[nt][0], acc[nt][3] + bcol[nt][1]);
                *(float2*)&y[((size_t)r0 * TT + (t - 1)) * OUTD + gcol] = v0;
                *(float2*)&y[((size_t)r1 * TT + (t - 1)) * OUTD + gcol] = v1;
            }
        }

        __syncthreads();        // all warps' h stores done before arrival
        bar_arrive();           // non-blocking; wait deferred to chunk 2
    }
}

extern "C" void kernel_launch(void* const* d_in, const int* in_sizes, int n_in,
                              void* d_out, int out_size) {
    (void)in_sizes; (void)n_in; (void)out_size;
    cudaFuncSetAttribute(lstm_mma, cudaFuncAttributeMaxDynamicSharedMemorySize, SMEM_TOTAL);
    lstm_mma<<<NCTA, NTHR, SMEM_TOTAL>>>(
        (const float*)d_in[0], (const float*)d_in[1], (const float*)d_in[2],
        (const float*)d_in[3], (const float*)d_in[4], (const float*)d_in[5],
        (const float*)d_in[6], (const float*)d_in[7], (float*)d_out);
}